// round 6
// baseline (speedup 1.0000x reference)
#include <cuda_runtime.h>

typedef unsigned long long u64;

#define B_    8
#define DIM_  1024
#define T_    4096
#define CB_   4096
#define CD_   8
#define BT_   (B_*T_)
#define NSL_  16
#define SLICE_ (CB_/NSL_)   // 256

static const size_t IDX_OFF_  = (size_t)B_ * DIM_ * T_;          // 33554432
static const size_t LOSS_OFF_ = (size_t)B_ * DIM_ * T_ + BT_;    // 33587200

// ---------------- device scratch (no allocations allowed) ----------------
__device__ float g_cn[CB_ * CD_];          // normalized codebook [j][c] (128 KB, L1-resident)
__device__ float g_Win[DIM_ * CD_];        // weight-normed in_proj, transposed [d][o]
__device__ float g_Wout2[DIM_ * 2 * CD_];  // weight-normed out_proj, splatted [o][c][2]
__device__ float g_bout2[DIM_ * 2];        // b_out splatted [o][2]
__device__ float g_ze[(size_t)BT_ * CD_];  // encodings z_e [t][c]  (1 MB)
__device__ float g_qp[(size_t)BT_ * CD_];  // gathered codes, pair-interleaved [tp][c][2]

// ---------------- f32x2 helpers ----------------
__device__ __forceinline__ u64 f2mul(u64 a, u64 b) {
    u64 r; asm("mul.rn.f32x2 %0, %1, %2;" : "=l"(r) : "l"(a), "l"(b)); return r;
}
__device__ __forceinline__ u64 f2fma(u64 a, u64 b, u64 c) {
    u64 r; asm("fma.rn.f32x2 %0, %1, %2, %3;" : "=l"(r) : "l"(a), "l"(b), "l"(c)); return r;
}
__device__ __forceinline__ float2 f2unpack(u64 a) {
    float x, y; asm("mov.b64 {%0, %1}, %2;" : "=f"(x), "=f"(y) : "l"(a));
    return make_float2(x, y);
}

// ---------------- prep ----------------
__global__ void __launch_bounds__(256) prep_kernel(
    const float* __restrict__ v_in, const float* __restrict__ g_in,
    const float* __restrict__ codebook,
    const float* __restrict__ v_out, const float* __restrict__ g_out,
    const float* __restrict__ b_out, float* __restrict__ dout)
{
    const int r = blockIdx.x * 256 + threadIdx.x;
    if (r < CB_) {
        float v[CD_]; float s = 0.f;
#pragma unroll
        for (int c = 0; c < CD_; ++c) { v[c] = codebook[(size_t)r * CD_ + c]; s += v[c] * v[c]; }
        float n = fmaxf(sqrtf(s), 1e-12f);
#pragma unroll
        for (int c = 0; c < CD_; ++c) g_cn[(size_t)r * CD_ + c] = v[c] / n;
    } else if (r < CB_ + DIM_) {
        const int o = r - CB_;
        float v[CD_]; float s = 0.f;
#pragma unroll
        for (int c = 0; c < CD_; ++c) { v[c] = v_out[(size_t)o * CD_ + c]; s += v[c] * v[c]; }
        float sc = g_out[o] / sqrtf(s);
#pragma unroll
        for (int c = 0; c < CD_; ++c) {
            float w = v[c] * sc;
            g_Wout2[o * 16 + 2 * c]     = w;
            g_Wout2[o * 16 + 2 * c + 1] = w;
        }
        float bb = b_out[o];
        g_bout2[o * 2] = bb; g_bout2[o * 2 + 1] = bb;
    } else if (r < CB_ + DIM_ + CD_ * 32) {
        const int idx  = r - (CB_ + DIM_);
        const int w    = idx >> 5;
        const int lane = idx & 31;
        float s = 0.f;
        for (int d = lane; d < DIM_; d += 32) {
            float v = v_in[(size_t)w * DIM_ + d]; s += v * v;
        }
#pragma unroll
        for (int off = 16; off > 0; off >>= 1) s += __shfl_xor_sync(0xffffffffu, s, off);
        float sc = g_in[w] / sqrtf(s);
        for (int d = lane; d < DIM_; d += 32)
            g_Win[d * CD_ + w] = v_in[(size_t)w * DIM_ + d] * sc;
    } else if (r < CB_ + DIM_ + CD_ * 32 + B_) {
        dout[LOSS_OFF_ + (r - (CB_ + DIM_ + CD_ * 32))] = 0.f;
    }
}

// ---------------- K1: z_e = W_in @ z + b_in  (DIM split 4-way; R2-proven) ----------------
__global__ void __launch_bounds__(256) ze_kernel(const float* __restrict__ z,
                                                 const float* __restrict__ b_in)
{
    const int tl = threadIdx.x & 63;
    const int dc = threadIdx.x >> 6;
    const int t  = blockIdx.x * 64 + tl;
    const int b  = t >> 12;
    const int tt = t & (T_ - 1);
    const float* zp = z + (size_t)b * DIM_ * T_ + tt + (size_t)(dc * 256) * T_;
    const float* wp = g_Win + dc * 256 * CD_;

    float a0 = 0.f, a1 = 0.f, a2 = 0.f, a3 = 0.f, a4 = 0.f, a5 = 0.f, a6 = 0.f, a7 = 0.f;
#pragma unroll 8
    for (int d = 0; d < 256; ++d) {
        float zv = __ldg(zp + (size_t)d * T_);
        float4 w0 = *(const float4*)(wp + d * CD_);
        float4 w1 = *(const float4*)(wp + d * CD_ + 4);
        a0 = fmaf(w0.x, zv, a0); a1 = fmaf(w0.y, zv, a1);
        a2 = fmaf(w0.z, zv, a2); a3 = fmaf(w0.w, zv, a3);
        a4 = fmaf(w1.x, zv, a4); a5 = fmaf(w1.y, zv, a5);
        a6 = fmaf(w1.z, zv, a6); a7 = fmaf(w1.w, zv, a7);
    }

    __shared__ float red[256 * 9];
    float* my = red + threadIdx.x * 9;
    my[0] = a0; my[1] = a1; my[2] = a2; my[3] = a3;
    my[4] = a4; my[5] = a5; my[6] = a6; my[7] = a7;
    __syncthreads();

    if (threadIdx.x < 64) {
        const int tg = blockIdx.x * 64 + threadIdx.x;
        float acc[CD_];
#pragma unroll
        for (int c = 0; c < CD_; ++c) acc[c] = __ldg(b_in + c);
#pragma unroll
        for (int k = 0; k < 4; ++k) {
            const float* p = red + (k * 64 + threadIdx.x) * 9;
#pragma unroll
            for (int c = 0; c < CD_; ++c) acc[c] += p[c];
        }
        float4* o = (float4*)(g_ze + (size_t)tg * CD_);
        o[0] = make_float4(acc[0], acc[1], acc[2], acc[3]);
        o[1] = make_float4(acc[4], acc[5], acc[6], acc[7]);
    }
}

// ---------------- K2: search + finalize fused ----------------
// Block = 512 threads = 16 warps. Warp w scans slice w (256 j) for 64 timesteps
// (2 per lane: t0 = tb+lane, t1 = tb+32+lane), SHARING the unsplatted codebook
// loads (2 LDG.128 per j, warp-uniform, L1-resident) across both timesteps.
__global__ void __launch_bounds__(512, 2) search_kernel(const float* __restrict__ codebook,
                                                        float* __restrict__ dout)
{
    __shared__ float s_bv[NSL_][64];
    __shared__ int   s_bi[NSL_][64];
    __shared__ int   s_idx[64];
    __shared__ float s_red[512];

    const int tid  = threadIdx.x;
    const int w    = tid >> 5;             // slice 0..15
    const int lane = tid & 31;
    const int tb   = blockIdx.x * 64;      // block's first timestep (within one batch)
    const int b    = tb >> 12;

    // z_e for two timesteps, as natural (e0,e1)(e2,e3)(e4,e5)(e6,e7) pairs
    const ulonglong2* zp0 = (const ulonglong2*)(g_ze + (size_t)(tb + lane) * CD_);
    const ulonglong2* zp1 = (const ulonglong2*)(g_ze + (size_t)(tb + 32 + lane) * CD_);
    ulonglong2 zA = zp0[0], zB = zp0[1];   // t0
    ulonglong2 zC = zp1[0], zD = zp1[1];   // t1

    float best0 = -3.4e38f, best1 = -3.4e38f;
    int i0 = 0, i1 = 0;

    const ulonglong2* cr = (const ulonglong2*)g_cn + (size_t)w * SLICE_ * 2;
#pragma unroll 2
    for (int j = 0; j < SLICE_; ++j) {
        ulonglong2 k0 = cr[2 * j], k1 = cr[2 * j + 1];   // warp-uniform, L1 broadcast

        u64 dA = f2mul(zA.x, k0.x);                      // t0 chain
        dA = f2fma(zA.y, k0.y, dA);
        dA = f2fma(zB.x, k1.x, dA);
        dA = f2fma(zB.y, k1.y, dA);
        u64 dB = f2mul(zC.x, k0.x);                      // t1 chain (same codebook regs)
        dB = f2fma(zC.y, k0.y, dB);
        dB = f2fma(zD.x, k1.x, dB);
        dB = f2fma(zD.y, k1.y, dB);

        float2 fa = f2unpack(dA);
        float2 fb = f2unpack(dB);
        float dot0 = fa.x + fa.y;
        float dot1 = fb.x + fb.y;
        if (dot0 > best0) { best0 = dot0; i0 = j; }      // strict > : lowest j on tie
        if (dot1 > best1) { best1 = dot1; i1 = j; }
    }

    s_bv[w][lane]      = best0;  s_bi[w][lane]      = i0 + w * SLICE_;
    s_bv[w][lane + 32] = best1;  s_bi[w][lane + 32] = i1 + w * SLICE_;
    __syncthreads();

    // merge across 16 slices (ascending keeps lowest global j on ties)
    if (tid < 64) {
        float bv = s_bv[0][tid]; int bi = s_bi[0][tid];
#pragma unroll
        for (int s = 1; s < NSL_; ++s) {
            float ov = s_bv[s][tid];
            if (ov > bv) { bv = ov; bi = s_bi[s][tid]; }
        }
        s_idx[tid] = bi;
        dout[IDX_OFF_ + tb + tid] = (float)bi;           // exactly representable
    }
    __syncthreads();

    // finalize: gather un-normalized codes, loss partial, pair-interleaved qp store
    {
        const int t = tid >> 3, c = tid & 7;             // t 0..63, c 0..7
        const int idx = s_idx[t];
        float qv = __ldg(codebook + (size_t)idx * CD_ + c);
        float ev = g_ze[(size_t)(tb + t) * CD_ + c];
        float d_ = ev - qv;
        s_red[tid] = d_ * d_;
        g_qp[(size_t)((tb + t) >> 1) * 16 + 2 * c + (t & 1)] = qv;
    }
    __syncthreads();
#pragma unroll
    for (int s = 256; s > 0; s >>= 1) {
        if (tid < s) s_red[tid] += s_red[tid + s];
        __syncthreads();
    }
    if (tid == 0)
        atomicAdd(&dout[LOSS_OFF_ + b], s_red[0] * (1.25f / 32768.f));
}

// ---------------- K3: out-proj. Warp owns 4 o-rows with weights IN REGISTERS ----------------
__global__ void __launch_bounds__(256) outproj_kernel(float* __restrict__ dout)
{
    const int w    = threadIdx.x >> 5;
    const int lane = threadIdx.x & 31;
    const int wg   = blockIdx.x * 8 + w;     // 0..16383
    const int quad = wg >> 6;                // o-quad 0..255  (warp-uniform)
    const int gch  = wg & 63;                // pair-group chunk 0..63

    // weights + bias for 4 output rows: loaded ONCE, live in registers
    u64 W[4][8]; u64 bias[4];
#pragma unroll
    for (int r = 0; r < 4; ++r) {
        const u64* wr = (const u64*)(g_Wout2 + (quad * 4 + r) * 16);
#pragma unroll
        for (int k = 0; k < 8; ++k) W[r][k] = wr[k];
        bias[r] = *(const u64*)(g_bout2 + (quad * 4 + r) * 2);
    }

#pragma unroll
    for (int it = 0; it < 8; ++it) {
        const int p  = (gch * 8 + it) * 32 + lane;   // t-pair, lanes consecutive
        const int t0 = p << 1;
        const int b  = t0 >> 12;
        const int tl = t0 & (T_ - 1);

        const u64* qr = (const u64*)(g_qp + (size_t)p * 16);
        u64 q0 = qr[0], q1 = qr[1], q2 = qr[2], q3 = qr[3];
        u64 q4 = qr[4], q5 = qr[5], q6 = qr[6], q7 = qr[7];

        float* outp = dout + ((size_t)b * DIM_ + quad * 4) * T_ + tl;
#pragma unroll
        for (int r = 0; r < 4; ++r) {
            u64 acc = bias[r];
            acc = f2fma(W[r][0], q0, acc);
            acc = f2fma(W[r][1], q1, acc);
            acc = f2fma(W[r][2], q2, acc);
            acc = f2fma(W[r][3], q3, acc);
            acc = f2fma(W[r][4], q4, acc);
            acc = f2fma(W[r][5], q5, acc);
            acc = f2fma(W[r][6], q6, acc);
            acc = f2fma(W[r][7], q7, acc);
            *(u64*)(outp + (size_t)r * T_) = acc;    // float2 store, coalesced 256B/warp
        }
    }
}

// ---------------- launcher ----------------
extern "C" void kernel_launch(void* const* d_in, const int* in_sizes, int n_in,
                              void* d_out, int out_size)
{
    const float* z        = (const float*)d_in[0];
    const float* v_in     = (const float*)d_in[1];
    const float* g_in     = (const float*)d_in[2];
    const float* b_in     = (const float*)d_in[3];
    const float* codebook = (const float*)d_in[4];
    const float* v_out    = (const float*)d_in[5];
    const float* g_out    = (const float*)d_in[6];
    const float* b_out    = (const float*)d_in[7];
    float* out = (float*)d_out;

    prep_kernel<<<22, 256>>>(v_in, g_in, codebook, v_out, g_out, b_out, out);
    ze_kernel<<<BT_ / 64, 256>>>(z, b_in);
    search_kernel<<<BT_ / 64, 512>>>(codebook, out);
    outproj_kernel<<<2048, 256>>>(out);
}

// round 7
// speedup vs baseline: 1.9263x; 1.9263x over previous
#include <cuda_runtime.h>

typedef unsigned long long u64;

#define B_    8
#define DIM_  1024
#define T_    4096
#define CB_   4096
#define CD_   8
#define BT_   (B_*T_)
#define NSL_  16
#define SLICE_ (CB_/NSL_)   // 256

static const size_t IDX_OFF_  = (size_t)B_ * DIM_ * T_;          // 33554432
static const size_t LOSS_OFF_ = (size_t)B_ * DIM_ * T_ + BT_;    // 33587200

// ---------------- device scratch (no allocations allowed) ----------------
__device__ float g_cn[CB_ * CD_];          // normalized codebook [j][c] (128 KB, L1-resident)
__device__ float g_Win2[DIM_ * 2 * CD_];   // weight-normed in_proj, transposed+splatted [d][c][2]
__device__ float g_bin2[2 * CD_];          // b_in splatted [c][2]
__device__ float g_Wout2[DIM_ * 2 * CD_];  // weight-normed out_proj, splatted [o][c][2]
__device__ float g_bout2[DIM_ * 2];        // b_out splatted [o][2]
__device__ float g_ze[(size_t)BT_ * CD_];  // encodings z_e [t][c]  (1 MB)
__device__ float g_qp[(size_t)BT_ * CD_];  // gathered codes, pair-interleaved [tp][c][2]

// ---------------- f32x2 helpers ----------------
__device__ __forceinline__ u64 f2mul(u64 a, u64 b) {
    u64 r; asm("mul.rn.f32x2 %0, %1, %2;" : "=l"(r) : "l"(a), "l"(b)); return r;
}
__device__ __forceinline__ u64 f2fma(u64 a, u64 b, u64 c) {
    u64 r; asm("fma.rn.f32x2 %0, %1, %2, %3;" : "=l"(r) : "l"(a), "l"(b), "l"(c)); return r;
}
__device__ __forceinline__ u64 f2add(u64 a, u64 b) {
    u64 r; asm("add.rn.f32x2 %0, %1, %2;" : "=l"(r) : "l"(a), "l"(b)); return r;
}
__device__ __forceinline__ float2 f2unpack(u64 a) {
    float x, y; asm("mov.b64 {%0, %1}, %2;" : "=f"(x), "=f"(y) : "l"(a));
    return make_float2(x, y);
}

// ---------------- prep ----------------
__global__ void __launch_bounds__(256) prep_kernel(
    const float* __restrict__ v_in, const float* __restrict__ g_in,
    const float* __restrict__ b_in,
    const float* __restrict__ codebook,
    const float* __restrict__ v_out, const float* __restrict__ g_out,
    const float* __restrict__ b_out, float* __restrict__ dout)
{
    const int r = blockIdx.x * 256 + threadIdx.x;
    if (r < CB_) {
        float v[CD_]; float s = 0.f;
#pragma unroll
        for (int c = 0; c < CD_; ++c) { v[c] = codebook[(size_t)r * CD_ + c]; s += v[c] * v[c]; }
        float n = fmaxf(sqrtf(s), 1e-12f);
#pragma unroll
        for (int c = 0; c < CD_; ++c) g_cn[(size_t)r * CD_ + c] = v[c] / n;
    } else if (r < CB_ + DIM_) {
        const int o = r - CB_;
        float v[CD_]; float s = 0.f;
#pragma unroll
        for (int c = 0; c < CD_; ++c) { v[c] = v_out[(size_t)o * CD_ + c]; s += v[c] * v[c]; }
        float sc = g_out[o] / sqrtf(s);
#pragma unroll
        for (int c = 0; c < CD_; ++c) {
            float w = v[c] * sc;
            g_Wout2[o * 16 + 2 * c]     = w;
            g_Wout2[o * 16 + 2 * c + 1] = w;
        }
        float bb = b_out[o];
        g_bout2[o * 2] = bb; g_bout2[o * 2 + 1] = bb;
    } else if (r < CB_ + DIM_ + CD_ * 32) {
        // in_proj: one warp per output channel; fill transposed+splatted W_in
        const int idx  = r - (CB_ + DIM_);
        const int w    = idx >> 5;
        const int lane = idx & 31;
        float s = 0.f;
        for (int d = lane; d < DIM_; d += 32) {
            float v = v_in[(size_t)w * DIM_ + d]; s += v * v;
        }
#pragma unroll
        for (int off = 16; off > 0; off >>= 1) s += __shfl_xor_sync(0xffffffffu, s, off);
        float sc = g_in[w] / sqrtf(s);
        for (int d = lane; d < DIM_; d += 32) {
            float val = v_in[(size_t)w * DIM_ + d] * sc;
            g_Win2[d * 16 + 2 * w]     = val;
            g_Win2[d * 16 + 2 * w + 1] = val;
        }
    } else if (r < CB_ + DIM_ + CD_ * 32 + CD_) {
        const int c = r - (CB_ + DIM_ + CD_ * 32);
        float bv = b_in[c];
        g_bin2[2 * c] = bv; g_bin2[2 * c + 1] = bv;
    } else if (r < CB_ + DIM_ + CD_ * 32 + CD_ + B_) {
        dout[LOSS_OFF_ + (r - (CB_ + DIM_ + CD_ * 32 + CD_))] = 0.f;
    }
}

// ---------------- K1: z_e via f32x2 timestep pairs ----------------
// Block = 512 threads = 16 warps; block covers 64 timesteps (32 adjacent pairs).
// Warp w reduces dim chunk [w*64, w*64+64); lane owns pair (t0 = tb+2*lane, t0+1).
// z load: one coalesced LDG.64 per d delivers BOTH timesteps.
__global__ void __launch_bounds__(512) ze_kernel(const float* __restrict__ z)
{
    __shared__ u64 s_part[16][32][CD_];    // 32 KB

    const int tid  = threadIdx.x;
    const int w    = tid >> 5;
    const int lane = tid & 31;
    const int tb   = blockIdx.x * 64;
    const int b    = tb >> 12;
    const int tt   = (tb & (T_ - 1)) + 2 * lane;

    const float* zp = z + ((size_t)b * DIM_ + w * 64) * T_ + tt;
    const float* wp = g_Win2 + (w * 64) * 16;

    u64 acc[CD_];
#pragma unroll
    for (int c = 0; c < CD_; ++c) acc[c] = 0ull;    // (0.0f, 0.0f)

#pragma unroll 8
    for (int d = 0; d < 64; ++d) {
        u64 zv = *(const u64*)(zp + (size_t)d * T_);           // 2 timesteps, coalesced
        const ulonglong2* wr = (const ulonglong2*)(wp + d * 16); // warp-uniform splat
        ulonglong2 w0 = wr[0], w1 = wr[1], w2 = wr[2], w3 = wr[3];
        acc[0] = f2fma(zv, w0.x, acc[0]);
        acc[1] = f2fma(zv, w0.y, acc[1]);
        acc[2] = f2fma(zv, w1.x, acc[2]);
        acc[3] = f2fma(zv, w1.y, acc[3]);
        acc[4] = f2fma(zv, w2.x, acc[4]);
        acc[5] = f2fma(zv, w2.y, acc[5]);
        acc[6] = f2fma(zv, w3.x, acc[6]);
        acc[7] = f2fma(zv, w3.y, acc[7]);
    }
#pragma unroll
    for (int c = 0; c < CD_; ++c) s_part[w][lane][c] = acc[c];
    __syncthreads();

    if (tid < 256) {
        const int tp = tid >> 3, c = tid & 7;
        u64 s = *(const u64*)(g_bin2 + 2 * c);
#pragma unroll
        for (int k = 0; k < 16; ++k) s = f2add(s, s_part[k][tp][c]);
        float2 f = f2unpack(s);
        g_ze[(size_t)(tb + 2 * tp) * CD_ + c]     = f.x;
        g_ze[(size_t)(tb + 2 * tp + 1) * CD_ + c] = f.y;
    }
}

// ---------------- K2: search + finalize fused (unchanged from R6) ----------------
__global__ void __launch_bounds__(512, 2) search_kernel(const float* __restrict__ codebook,
                                                        float* __restrict__ dout)
{
    __shared__ float s_bv[NSL_][64];
    __shared__ int   s_bi[NSL_][64];
    __shared__ int   s_idx[64];
    __shared__ float s_red[512];

    const int tid  = threadIdx.x;
    const int w    = tid >> 5;             // slice 0..15
    const int lane = tid & 31;
    const int tb   = blockIdx.x * 64;
    const int b    = tb >> 12;

    const ulonglong2* zp0 = (const ulonglong2*)(g_ze + (size_t)(tb + lane) * CD_);
    const ulonglong2* zp1 = (const ulonglong2*)(g_ze + (size_t)(tb + 32 + lane) * CD_);
    ulonglong2 zA = zp0[0], zB = zp0[1];   // t0
    ulonglong2 zC = zp1[0], zD = zp1[1];   // t1

    float best0 = -3.4e38f, best1 = -3.4e38f;
    int i0 = 0, i1 = 0;

    const ulonglong2* cr = (const ulonglong2*)g_cn + (size_t)w * SLICE_ * 2;
#pragma unroll 2
    for (int j = 0; j < SLICE_; ++j) {
        ulonglong2 k0 = cr[2 * j], k1 = cr[2 * j + 1];   // warp-uniform, L1 broadcast

        u64 dA = f2mul(zA.x, k0.x);
        dA = f2fma(zA.y, k0.y, dA);
        dA = f2fma(zB.x, k1.x, dA);
        dA = f2fma(zB.y, k1.y, dA);
        u64 dB = f2mul(zC.x, k0.x);
        dB = f2fma(zC.y, k0.y, dB);
        dB = f2fma(zD.x, k1.x, dB);
        dB = f2fma(zD.y, k1.y, dB);

        float2 fa = f2unpack(dA);
        float2 fb = f2unpack(dB);
        float dot0 = fa.x + fa.y;
        float dot1 = fb.x + fb.y;
        if (dot0 > best0) { best0 = dot0; i0 = j; }      // strict > : lowest j on tie
        if (dot1 > best1) { best1 = dot1; i1 = j; }
    }

    s_bv[w][lane]      = best0;  s_bi[w][lane]      = i0 + w * SLICE_;
    s_bv[w][lane + 32] = best1;  s_bi[w][lane + 32] = i1 + w * SLICE_;
    __syncthreads();

    if (tid < 64) {
        float bv = s_bv[0][tid]; int bi = s_bi[0][tid];
#pragma unroll
        for (int s = 1; s < NSL_; ++s) {
            float ov = s_bv[s][tid];
            if (ov > bv) { bv = ov; bi = s_bi[s][tid]; }  // ascending s keeps lowest j
        }
        s_idx[tid] = bi;
        dout[IDX_OFF_ + tb + tid] = (float)bi;
    }
    __syncthreads();

    {
        const int t = tid >> 3, c = tid & 7;
        const int idx = s_idx[t];
        float qv = __ldg(codebook + (size_t)idx * CD_ + c);
        float ev = g_ze[(size_t)(tb + t) * CD_ + c];
        float d_ = ev - qv;
        s_red[tid] = d_ * d_;
        g_qp[(size_t)((tb + t) >> 1) * 16 + 2 * c + (t & 1)] = qv;
    }
    __syncthreads();
#pragma unroll
    for (int s = 256; s > 0; s >>= 1) {
        if (tid < s) s_red[tid] += s_red[tid + s];
        __syncthreads();
    }
    if (tid == 0)
        atomicAdd(&dout[LOSS_OFF_ + b], s_red[0] * (1.25f / 32768.f));
}

// ---------------- K3: out-proj, smem-staged ----------------
// Block = 256 threads; covers 64 o-rows x 128 t-pairs.
// Weights/biases/q-tile staged in smem (12.5 KB); weights read via warp-uniform
// LDS broadcast, q held in 8 u64 registers. Low regs -> high occupancy.
__global__ void __launch_bounds__(256) outproj_kernel(float* __restrict__ dout)
{
    __shared__ float s_w[64 * 16];     // splatted weights, 4 KB
    __shared__ float s_b[64 * 2];      // splatted bias
    __shared__ float s_q[128 * 16];    // q tile, 8 KB

    const int tid = threadIdx.x;
    const int oc  = blockIdx.x & 15;          // o-row chunk 0..15
    const int pc  = blockIdx.x >> 4;          // pair chunk 0..127

    // stage weights + bias + q (all coalesced)
    ((float4*)s_w)[tid] = ((const float4*)(g_Wout2 + oc * 64 * 16))[tid];
    if (tid < 32) ((float4*)s_b)[tid] = ((const float4*)(g_bout2 + oc * 64 * 2))[tid];
    ((float4*)s_q)[tid]       = ((const float4*)(g_qp + (size_t)pc * 128 * 16))[tid];
    ((float4*)s_q)[tid + 256] = ((const float4*)(g_qp + (size_t)pc * 128 * 16))[tid + 256];
    __syncthreads();

    const int wrp  = tid >> 5;
    const int lane = tid & 31;
    const int pg   = wrp & 3;                 // pair group 0..3
    const int rh   = (wrp >> 2) * 32;         // row half: 0 or 32
    const int pl   = pg * 32 + lane;          // pair within tile 0..127

    // q for this thread's pair: 8 u64 in registers
    const u64* qs = (const u64*)(s_q + pl * 16);
    u64 q0 = qs[0], q1 = qs[1], q2 = qs[2], q3 = qs[3];
    u64 q4 = qs[4], q5 = qs[5], q6 = qs[6], q7 = qs[7];

    const int t0 = (pc * 128 + pl) * 2;
    const int b  = t0 >> 12;
    const int tl = t0 & (T_ - 1);
    float* outp = dout + ((size_t)b * DIM_ + oc * 64 + rh) * T_ + tl;

#pragma unroll 4
    for (int r = 0; r < 32; ++r) {
        const ulonglong2* wr = (const ulonglong2*)(s_w + (rh + r) * 16);  // uniform LDS
        ulonglong2 w0 = wr[0], w1 = wr[1], w2 = wr[2], w3 = wr[3];
        u64 acc = *(const u64*)(s_b + (rh + r) * 2);
        acc = f2fma(w0.x, q0, acc);
        acc = f2fma(w0.y, q1, acc);
        acc = f2fma(w1.x, q2, acc);
        acc = f2fma(w1.y, q3, acc);
        acc = f2fma(w2.x, q4, acc);
        acc = f2fma(w2.y, q5, acc);
        acc = f2fma(w3.x, q6, acc);
        acc = f2fma(w3.y, q7, acc);
        *(u64*)(outp + (size_t)r * T_) = acc;    // float2 store, 256B/warp coalesced
    }
}

// ---------------- launcher ----------------
extern "C" void kernel_launch(void* const* d_in, const int* in_sizes, int n_in,
                              void* d_out, int out_size)
{
    const float* z        = (const float*)d_in[0];
    const float* v_in     = (const float*)d_in[1];
    const float* g_in     = (const float*)d_in[2];
    const float* b_in     = (const float*)d_in[3];
    const float* codebook = (const float*)d_in[4];
    const float* v_out    = (const float*)d_in[5];
    const float* g_out    = (const float*)d_in[6];
    const float* b_out    = (const float*)d_in[7];
    float* out = (float*)d_out;

    prep_kernel<<<22, 256>>>(v_in, g_in, b_in, codebook, v_out, g_out, b_out, out);
    ze_kernel<<<BT_ / 64, 512>>>(z);
    search_kernel<<<BT_ / 64, 512>>>(codebook, out);
    outproj_kernel<<<2048, 256>>>(out);
}